// round 2
// baseline (speedup 1.0000x reference)
#include <cuda_runtime.h>

#define HDIM 64
#define DDIM 32

typedef unsigned long long u64;

// Precomputed per-launch vectors (written by precompute_kernel, read by gate_kernel)
__device__ float g_c[HDIM];   // c = W_fc[:,0:64]@h[idx] + b_fc + (W3+W4)@b_emb
__device__ float g_u2[HDIM];  // u2 = W_fc[:,160:192]@w_sum

__device__ __forceinline__ u64 fma2(u64 a, u64 b, u64 c) {
    u64 d;
    asm("fma.rn.f32x2 %0, %1, %2, %3;" : "=l"(d) : "l"(a), "l"(b), "l"(c));
    return d;
}

__device__ __forceinline__ u64 pack2(float lo, float hi) {
    u64 v;
    asm("mov.b64 %0, {%1, %2};" : "=l"(v) : "f"(lo), "f"(hi));
    return v;
}

__device__ __forceinline__ float2 unpack2(u64 v) {
    float lo, hi;
    asm("mov.b64 {%0, %1}, %2;" : "=f"(lo), "=f"(hi) : "l"(v));
    return make_float2(lo, hi);
}

// sigmoid(z) = 1 / (1 + 2^(-z*log2e)) via MUFU EX2 + RCP (SFU pipe, ~1e-6 rel err)
__device__ __forceinline__ float sigmoid_fast(float z) {
    float e, r;
    asm("ex2.approx.f32 %0, %1;" : "=f"(e) : "f"(z * -1.44269504088896340736f));
    asm("rcp.approx.f32 %0, %1;" : "=f"(r) : "f"(1.0f + e));
    return r;
}

// One small block: folds all per-launch constants and writes goal_out.
__global__ void precompute_kernel(const float* __restrict__ h,
                                  const float* __restrict__ ghs,
                                  const float* __restrict__ goal,
                                  const float* __restrict__ position,
                                  const float* __restrict__ W_emb,
                                  const float* __restrict__ b_emb,
                                  const float* __restrict__ W_fc,
                                  const float* __restrict__ b_fc,
                                  const int* __restrict__ idx_ptr,
                                  float* __restrict__ out, int n)
{
    int j = threadIdx.x;
    if (j >= HDIM) return;
    int idx = idx_ptr[0];
    float px = position[2 * idx], py = position[2 * idx + 1];
    float gx = goal[2 * idx],     gy = goal[2 * idx + 1];
    float ddx = px - gx, ddy = py - gy;
    float dgn = sqrtf(ddx * ddx + ddy * ddy);

    const float* Wj = W_fc + j * 192;
    const float* hi = h + (size_t)idx * HDIM;

    float c0 = 0.f, wg = 0.f;
    #pragma unroll 8
    for (int k = 0; k < HDIM; k++) {
        c0 += Wj[k] * hi[k];
        wg += Wj[64 + k] * ghs[k];
    }
    float u1 = 0.f, u2 = 0.f, cb = 0.f;
    #pragma unroll 8
    for (int d = 0; d < DDIM; d++) {
        float ws = W_emb[2 * d] + W_emb[2 * d + 1];
        u1 += Wj[128 + d] * ws;
        u2 += Wj[160 + d] * ws;
        cb += (Wj[128 + d] + Wj[160 + d]) * b_emb[d];
    }
    float c = c0 + b_fc[j] + cb;
    g_c[j]  = c;
    g_u2[j] = u2;

    // goal_out = sigmoid(c + W2@goal_hidden + dg*(u1+u2)); accurate expf off hot path
    float zg = c + wg + dgn * (u1 + u2);
    out[(size_t)n * HDIM + j] = 1.0f / (1.0f + expf(-zg));
}

// Main kernel: out[r] = sigmoid(W2 @ h[r] + d2[r]*u2 + c), d2 = ||goal[r]-position[r]||
// One thread per agent row; W2^T in shared (broadcast LDS); packed f32x2 FMAs.
__global__ __launch_bounds__(256, 2)
void gate_kernel(const float* __restrict__ h,
                 const float* __restrict__ goal,
                 const float* __restrict__ position,
                 const float* __restrict__ W_fc,
                 const int* __restrict__ idx_ptr,
                 float* __restrict__ out, int n)
{
    __shared__ __align__(16) float sW[HDIM * HDIM];  // sW[k*64+j] = W_fc[j,64+k] (W2^T)
    __shared__ __align__(16) float sC[HDIM];
    __shared__ __align__(16) float sU[HDIM];

    int t = threadIdx.x;
    for (int e = t; e < HDIM * HDIM; e += 256) {
        int k = e >> 6, j = e & 63;
        sW[e] = W_fc[j * 192 + 64 + k];
    }
    if (t < HDIM) { sC[t] = g_c[t]; sU[t] = g_u2[t]; }
    __syncthreads();

    int r = blockIdx.x * 256 + t;
    if (r >= n) return;
    int idx = idx_ptr[0];

    float2 g = ((const float2*)goal)[r];
    float2 p = ((const float2*)position)[r];
    float dx = g.x - p.x, dy = g.y - p.y;
    float d2 = sqrtf(dx * dx + dy * dy);
    u64 d2p = pack2(d2, d2);

    // acc[m] holds outputs j = 2m, 2m+1; init with c + d2*u2
    u64 acc[32];
    const u64* cP = (const u64*)sC;
    const u64* uP = (const u64*)sU;
    #pragma unroll
    for (int i = 0; i < 32; i++) acc[i] = fma2(d2p, uP[i], cP[i]);

    const float4* hrow = (const float4*)(h + (size_t)r * HDIM);
    #pragma unroll
    for (int kc = 0; kc < 4; kc++) {
        float4 hb0 = hrow[kc * 4 + 0];
        float4 hb1 = hrow[kc * 4 + 1];
        float4 hb2 = hrow[kc * 4 + 2];
        float4 hb3 = hrow[kc * 4 + 3];
        float hv[16] = {hb0.x, hb0.y, hb0.z, hb0.w,
                        hb1.x, hb1.y, hb1.z, hb1.w,
                        hb2.x, hb2.y, hb2.z, hb2.w,
                        hb3.x, hb3.y, hb3.z, hb3.w};
        #pragma unroll
        for (int kk = 0; kk < 16; kk++) {
            u64 hk2 = pack2(hv[kk], hv[kk]);
            const ulonglong2* w = (const ulonglong2*)(sW + (kc * 16 + kk) * HDIM);
            #pragma unroll
            for (int i = 0; i < 16; i++) {
                ulonglong2 wv = w[i];                 // broadcast, conflict-free
                acc[2 * i]     = fma2(wv.x, hk2, acc[2 * i]);
                acc[2 * i + 1] = fma2(wv.y, hk2, acc[2 * i + 1]);
            }
        }
    }

    float4* orow = (float4*)(out + (size_t)r * HDIM);
    if (r == idx) {
        // row idx is passed through unchanged
        #pragma unroll
        for (int i = 0; i < 16; i++) orow[i] = hrow[i];
    } else {
        #pragma unroll
        for (int i = 0; i < 16; i++) {
            float2 a = unpack2(acc[2 * i]);
            float2 b = unpack2(acc[2 * i + 1]);
            float4 o;
            o.x = sigmoid_fast(a.x);
            o.y = sigmoid_fast(a.y);
            o.z = sigmoid_fast(b.x);
            o.w = sigmoid_fast(b.y);
            orow[i] = o;
        }
    }
}

extern "C" void kernel_launch(void* const* d_in, const int* in_sizes, int n_in,
                              void* d_out, int out_size)
{
    const float* h    = (const float*)d_in[0];  // (N, 64)
    const float* ghs  = (const float*)d_in[1];  // (64,)
    const float* goal = (const float*)d_in[2];  // (N, 2)
    const float* pos  = (const float*)d_in[3];  // (N, 2)
    const float* Wemb = (const float*)d_in[4];  // (32, 2)
    const float* bemb = (const float*)d_in[5];  // (32,)
    const float* Wfc  = (const float*)d_in[6];  // (64, 192)
    const float* bfc  = (const float*)d_in[7];  // (64,)
    const int*   idx  = (const int*)d_in[8];    // scalar
    float* out = (float*)d_out;                 // N*64 h_out then 64 goal_out

    int n = in_sizes[0] / HDIM;

    precompute_kernel<<<1, 64>>>(h, ghs, goal, pos, Wemb, bemb, Wfc, bfc, idx, out, n);
    gate_kernel<<<(n + 255) / 256, 256>>>(h, goal, pos, Wfc, idx, out, n);
}

// round 5
// speedup vs baseline: 2.6109x; 2.6109x over previous
#include <cuda_runtime.h>
#include <cstdint>

#define HDIM 64
#define DDIM 32

// Precomputed per-launch vectors (written by precompute_kernel, read by gate_kernel)
__device__ float g_c[HDIM];   // c = W_fc[:,0:64]@h[idx] + b_fc + (W3+W4)@b_emb
__device__ float g_u2[HDIM];  // u2 = W_fc[:,160:192]@w_sum

__device__ __forceinline__ float sigmoid_fast(float z) {
    float e, r;
    asm("ex2.approx.f32 %0, %1;" : "=f"(e) : "f"(z * -1.44269504088896340736f));
    asm("rcp.approx.f32 %0, %1;" : "=f"(r) : "f"(1.0f + e));
    return r;
}

__device__ __forceinline__ uint32_t to_tf32(float x) {
    uint32_t r;
    asm("cvt.rna.tf32.f32 %0, %1;" : "=r"(r) : "f"(x));
    return r;
}

__device__ __forceinline__ void mma_tf32(float* c, uint32_t a0, uint32_t a1,
                                         uint32_t a2, uint32_t a3,
                                         uint32_t b0, uint32_t b1) {
    asm volatile(
        "mma.sync.aligned.m16n8k8.row.col.f32.tf32.tf32.f32 "
        "{%0,%1,%2,%3}, {%4,%5,%6,%7}, {%8,%9}, {%0,%1,%2,%3};"
        : "+f"(c[0]), "+f"(c[1]), "+f"(c[2]), "+f"(c[3])
        : "r"(a0), "r"(a1), "r"(a2), "r"(a3), "r"(b0), "r"(b1));
}

// ---------------- precompute (per-launch constants + goal_out) ----------------

__global__ void precompute_kernel(const float* __restrict__ h,
                                  const float* __restrict__ ghs,
                                  const float* __restrict__ goal,
                                  const float* __restrict__ position,
                                  const float* __restrict__ W_emb,
                                  const float* __restrict__ b_emb,
                                  const float* __restrict__ W_fc,
                                  const float* __restrict__ b_fc,
                                  const int* __restrict__ idx_ptr,
                                  float* __restrict__ out, int n)
{
    int j = threadIdx.x;
    if (j >= HDIM) return;
    int idx = idx_ptr[0];
    float px = position[2 * idx], py = position[2 * idx + 1];
    float gx = goal[2 * idx],     gy = goal[2 * idx + 1];
    float ddx = px - gx, ddy = py - gy;
    float dgn = sqrtf(ddx * ddx + ddy * ddy);

    const float* Wj = W_fc + j * 192;
    const float* hi = h + (size_t)idx * HDIM;

    float c0 = 0.f, wg = 0.f;
    #pragma unroll 8
    for (int k = 0; k < HDIM; k++) {
        c0 += Wj[k] * hi[k];
        wg += Wj[64 + k] * ghs[k];
    }
    float u1 = 0.f, u2 = 0.f, cb = 0.f;
    #pragma unroll 8
    for (int d = 0; d < DDIM; d++) {
        float ws = W_emb[2 * d] + W_emb[2 * d + 1];
        u1 += Wj[128 + d] * ws;
        u2 += Wj[160 + d] * ws;
        cb += (Wj[128 + d] + Wj[160 + d]) * b_emb[d];
    }
    float c = c0 + b_fc[j] + cb;
    g_c[j]  = c;
    g_u2[j] = u2;

    float zg = c + wg + dgn * (u1 + u2);
    out[(size_t)n * HDIM + j] = 1.0f / (1.0f + expf(-zg));
}

// ---------------- main kernel: mma.sync tf32 GEMV-batch + fused epilogue ----
// out[r] = sigmoid(W2 @ h[r] + d2[r]*u2 + c);  row idx passed through.
//
// Persistent CTAs, 8 warps. Per chunk iteration: 32 rows. Warp w handles the
// (w>>2)-th 16-row half and 16 output cols [(w&3)*16, +16) as two m16n8 tiles.
// K-permutation: fragment col t <-> physical 2t, t+4 <-> 2t+1 (same perm on
// B's k-rows) => all fragment loads are contiguous LDG.64. No shared memory.

__global__ __launch_bounds__(256, 2)
void gate_kernel(const float* __restrict__ h,
                 const float* __restrict__ goal,
                 const float* __restrict__ position,
                 const float* __restrict__ W_fc,
                 const int* __restrict__ idx_ptr,
                 float* __restrict__ out, int n)
{
    int t = threadIdx.x;
    int w = t >> 5, lane = t & 31;
    int g  = lane >> 2;          // 0..7
    int tq = lane & 3;           // 0..3
    int half = w >> 2;           // which 16-row half of the 32-row chunk
    int wq   = w & 3;            // which 16-col quarter
    int idx  = idx_ptr[0];

    // B fragments in registers: bf[nt][s][0..1], tf32-converted.
    // b0 = W2^T[k0+2tq][j], b1 = W2^T[k0+2tq+1][j], j = wq*16 + nt*8 + g
    uint32_t bf[2][8][2];
    #pragma unroll
    for (int nt = 0; nt < 2; nt++) {
        const float* Wrow = W_fc + (size_t)(wq * 16 + nt * 8 + g) * 192 + 64 + 2 * tq;
        #pragma unroll
        for (int s = 0; s < 8; s++) {
            float2 bv = *(const float2*)(Wrow + s * 8);
            bf[nt][s][0] = to_tf32(bv.x);
            bf[nt][s][1] = to_tf32(bv.y);
        }
    }

    // Per-lane epilogue constants: cols j0+{0,1} for nt=0,1 (j0 = wq*16+nt*8+2tq)
    float cc[2][2], uu[2][2];
    #pragma unroll
    for (int nt = 0; nt < 2; nt++) {
        int jc = wq * 16 + nt * 8 + 2 * tq;
        cc[nt][0] = g_c[jc];     cc[nt][1] = g_c[jc + 1];
        uu[nt][0] = g_u2[jc];    uu[nt][1] = g_u2[jc + 1];
    }

    const float2* goal2 = (const float2*)goal;
    const float2* pos2  = (const float2*)position;

    int nch = (n + 31) >> 5;
    for (int ch = blockIdx.x; ch < nch; ch += gridDim.x) {
        int rbase = ch * 32 + half * 16;
        int rg = rbase + g;          // rows g .. g+7 of this 16-row half
        int r8 = rbase + g + 8;
        bool vg = rg < n, v8 = r8 < n;

        // A fragment loads (front-batched, MLP=16): lane reads cols [2tq, 2tq+1]
        // of k-block s for its two rows.
        float2 aL[8], aH[8];
        const float2 z2 = make_float2(0.f, 0.f);
        const float* hg = h + (size_t)rg * HDIM + 2 * tq;
        const float* h8 = h + (size_t)r8 * HDIM + 2 * tq;
        #pragma unroll
        for (int s = 0; s < 8; s++) aL[s] = vg ? *(const float2*)(hg + s * 8) : z2;
        #pragma unroll
        for (int s = 0; s < 8; s++) aH[s] = v8 ? *(const float2*)(h8 + s * 8) : z2;

        // d2 for the two rows this lane owns
        float d2a = 0.f, d2b = 0.f;
        if (vg) {
            float2 gg = goal2[rg], pp = pos2[rg];
            float dx = gg.x - pp.x, dy = gg.y - pp.y;
            d2a = sqrtf(dx * dx + dy * dy);
        }
        if (v8) {
            float2 gg = goal2[r8], pp = pos2[r8];
            float dx = gg.x - pp.x, dy = gg.y - pp.y;
            d2b = sqrtf(dx * dx + dy * dy);
        }

        float acc[2][4] = {{0.f, 0.f, 0.f, 0.f}, {0.f, 0.f, 0.f, 0.f}};
        #pragma unroll
        for (int s = 0; s < 8; s++) {
            uint32_t a0 = to_tf32(aL[s].x);   // frag (g,   tq)   = phys col 2tq
            uint32_t a2 = to_tf32(aL[s].y);   // frag (g,   tq+4) = phys col 2tq+1
            uint32_t a1 = to_tf32(aH[s].x);   // frag (g+8, tq)
            uint32_t a3 = to_tf32(aH[s].y);   // frag (g+8, tq+4)
            mma_tf32(acc[0], a0, a1, a2, a3, bf[0][s][0], bf[0][s][1]);
            mma_tf32(acc[1], a0, a1, a2, a3, bf[1][s][0], bf[1][s][1]);
        }

        // Epilogue: c0,c1 -> row rg cols (jc, jc+1); c2,c3 -> row r8
        #pragma unroll
        for (int nt = 0; nt < 2; nt++) {
            int jc = wq * 16 + nt * 8 + 2 * tq;
            if (vg) {
                float2 o;
                o.x = sigmoid_fast(fmaf(d2a, uu[nt][0], acc[nt][0] + cc[nt][0]));
                o.y = sigmoid_fast(fmaf(d2a, uu[nt][1], acc[nt][1] + cc[nt][1]));
                if (rg == idx) o = *(const float2*)(h + (size_t)rg * HDIM + jc);
                *(float2*)(out + (size_t)rg * HDIM + jc) = o;
            }
            if (v8) {
                float2 o;
                o.x = sigmoid_fast(fmaf(d2b, uu[nt][0], acc[nt][2] + cc[nt][0]));
                o.y = sigmoid_fast(fmaf(d2b, uu[nt][1], acc[nt][3] + cc[nt][1]));
                if (r8 == idx) o = *(const float2*)(h + (size_t)r8 * HDIM + jc);
                *(float2*)(out + (size_t)r8 * HDIM + jc) = o;
            }
        }
    }
}

// ---------------- launch ----------------

extern "C" void kernel_launch(void* const* d_in, const int* in_sizes, int n_in,
                              void* d_out, int out_size)
{
    const float* h    = (const float*)d_in[0];  // (N, 64)
    const float* ghs  = (const float*)d_in[1];  // (64,)
    const float* goal = (const float*)d_in[2];  // (N, 2)
    const float* pos  = (const float*)d_in[3];  // (N, 2)
    const float* Wemb = (const float*)d_in[4];  // (32, 2)
    const float* bemb = (const float*)d_in[5];  // (32,)
    const float* Wfc  = (const float*)d_in[6];  // (64, 192)
    const float* bfc  = (const float*)d_in[7];  // (64,)
    const int*   idx  = (const int*)d_in[8];    // scalar
    float* out = (float*)d_out;                 // N*64 h_out then 64 goal_out

    int n = in_sizes[0] / HDIM;
    int nch = (n + 31) / 32;
    int grid = 296;                              // 148 SMs x 2 CTAs (persistent)
    if (grid > nch) grid = nch;

    precompute_kernel<<<1, 64>>>(h, ghs, goal, pos, Wemb, bemb, Wfc, bfc, idx, out, n);
    gate_kernel<<<grid, 256>>>(h, goal, pos, Wfc, idx, out, n);
}

// round 6
// speedup vs baseline: 4.2857x; 1.6415x over previous
#include <cuda_runtime.h>
#include <cstdint>

#define HDIM 64
#define DDIM 32

__device__ __forceinline__ float sigmoid_fast(float z) {
    float e, r;
    asm("ex2.approx.f32 %0, %1;" : "=f"(e) : "f"(z * -1.44269504088896340736f));
    asm("rcp.approx.f32 %0, %1;" : "=f"(r) : "f"(1.0f + e));
    return r;
}

__device__ __forceinline__ uint32_t to_tf32(float x) {
    uint32_t r;
    asm("cvt.rna.tf32.f32 %0, %1;" : "=r"(r) : "f"(x));
    return r;
}

__device__ __forceinline__ void mma_tf32(float* c, uint32_t a0, uint32_t a1,
                                         uint32_t a2, uint32_t a3,
                                         uint32_t b0, uint32_t b1) {
    asm volatile(
        "mma.sync.aligned.m16n8k8.row.col.f32.tf32.tf32.f32 "
        "{%0,%1,%2,%3}, {%4,%5,%6,%7}, {%8,%9}, {%0,%1,%2,%3};"
        : "+f"(c[0]), "+f"(c[1]), "+f"(c[2]), "+f"(c[3])
        : "r"(a0), "r"(a1), "r"(a2), "r"(a3), "r"(b0), "r"(b1));
}

// ---------------------------------------------------------------------------
// Single fused kernel.
// out[r] = sigmoid(W2 @ h[r] + d2[r]*u2 + c),  d2[r] = ||goal[r]-position[r]||,
// row idx passed through; goal_out written by CTA 0.
//
// K-permutation (applied identically to A cols and B k-rows; exact):
//   phys k-col = 16*S + 4*tau + e  <->  frag (s = 2S + (e>>1), kappa = tau + 4*(e&1))
// N-permutation (output cols / B rows):
//   phys J = wq*32 + sg*16 + 4*tau + e <-> (nt = 2*sg + (e>>1), fragn = 2*tau + (e&1))
// => every fragment load is LDG.128, every store is STG.128.
//
// Warp w of 8: rgrp = w>>1 (16-row group of the 64-row chunk), wq = w&1
// (32-col half). B frags: 4 n-tiles x 4 S = 16 uint4 (64 regs), loaded once.
// ---------------------------------------------------------------------------

__global__ __launch_bounds__(256, 2)
void gate_kernel(const float* __restrict__ h,
                 const float* __restrict__ ghs,
                 const float* __restrict__ goal,
                 const float* __restrict__ position,
                 const float* __restrict__ W_emb,
                 const float* __restrict__ b_emb,
                 const float* __restrict__ W_fc,
                 const float* __restrict__ b_fc,
                 const int* __restrict__ idx_ptr,
                 float* __restrict__ out, int n)
{
    __shared__ __align__(16) float sC[HDIM];
    __shared__ __align__(16) float sU[HDIM];

    const int t = threadIdx.x;
    const int idx = idx_ptr[0];

    // ---- per-CTA precompute of c[j], u2[j] (threads 0..63) ----
    if (t < HDIM) {
        const int j = t;
        const float* Wj = W_fc + j * 192;
        const float* hi = h + (size_t)idx * HDIM;
        float c0 = 0.f;
        #pragma unroll 8
        for (int k = 0; k < HDIM; k++) c0 += Wj[k] * hi[k];
        float u1 = 0.f, u2 = 0.f, cb = 0.f;
        #pragma unroll 8
        for (int d = 0; d < DDIM; d++) {
            float ws = W_emb[2 * d] + W_emb[2 * d + 1];
            u1 += Wj[128 + d] * ws;
            u2 += Wj[160 + d] * ws;
            cb += (Wj[128 + d] + Wj[160 + d]) * b_emb[d];
        }
        float c = c0 + b_fc[j] + cb;
        sC[j] = c;
        sU[j] = u2;

        if (blockIdx.x == 0) {
            float wg = 0.f;
            #pragma unroll 8
            for (int k = 0; k < HDIM; k++) wg += Wj[64 + k] * ghs[k];
            float px = position[2 * idx], py = position[2 * idx + 1];
            float gx = goal[2 * idx],     gy = goal[2 * idx + 1];
            float ddx = px - gx, ddy = py - gy;
            float dgn = sqrtf(ddx * ddx + ddy * ddy);
            float zg = c + wg + dgn * (u1 + u2);
            out[(size_t)n * HDIM + j] = 1.0f / (1.0f + expf(-zg));
        }
    }
    __syncthreads();

    const int w    = t >> 5;
    const int lane = t & 31;
    const int g    = lane >> 2;      // 0..7
    const int tau  = lane & 3;       // 0..3
    const int rgrp = w >> 1;         // 0..3 : 16-row group within 64-row chunk
    const int wq   = w & 1;          // 0..1 : 32-col half

    // ---- B fragments: bf[nt][S], tf32-converted. j = J(nt, g). ----
    uint4 bf[4][4];
    #pragma unroll
    for (int nt = 0; nt < 4; nt++) {
        int j = wq * 32 + (nt >> 1) * 16 + 4 * (g >> 1) + 2 * (nt & 1) + (g & 1);
        const float* Wrow = W_fc + (size_t)j * 192 + 64 + 4 * tau;
        #pragma unroll
        for (int S = 0; S < 4; S++) {
            float4 bv = *(const float4*)(Wrow + 16 * S);
            bf[nt][S].x = to_tf32(bv.x);
            bf[nt][S].y = to_tf32(bv.y);
            bf[nt][S].z = to_tf32(bv.z);
            bf[nt][S].w = to_tf32(bv.w);
        }
    }

    const float2* goal2 = (const float2*)goal;
    const float2* pos2  = (const float2*)position;
    const float4* h4    = (const float4*)h;
    float4* out4        = (float4*)out;
    const float4* sC4   = (const float4*)sC;
    const float4* sU4   = (const float4*)sU;

    // contiguous chunk range per CTA (64 rows per chunk)
    const int nch = (n + 63) >> 6;
    const int per = (nch + gridDim.x - 1) / gridDim.x;
    const int cA = blockIdx.x * per;
    int cB = cA + per; if (cB > nch) cB = nch;

    for (int ch = cA; ch < cB; ch++) {
        const int rbase = ch * 64 + rgrp * 16;
        const int rg = rbase + g;
        const int r8 = rbase + g + 8;
        const bool vg = rg < n, v8 = r8 < n;

        // ---- A fragment loads: 8x LDG.128, front-batched ----
        float4 aL[4], aH[4];
        const float4 z4 = make_float4(0.f, 0.f, 0.f, 0.f);
        const float4* hg = h4 + (size_t)rg * 16 + tau;   // +4S float4s
        const float4* h8r = h4 + (size_t)r8 * 16 + tau;
        #pragma unroll
        for (int S = 0; S < 4; S++) aL[S] = vg ? hg[4 * S] : z4;
        #pragma unroll
        for (int S = 0; S < 4; S++) aH[S] = v8 ? h8r[4 * S] : z4;

        float d2a = 0.f, d2b = 0.f;
        if (vg) {
            float2 gg = goal2[rg], pp = pos2[rg];
            float dx = gg.x - pp.x, dy = gg.y - pp.y;
            d2a = sqrtf(dx * dx + dy * dy);
        }
        if (v8) {
            float2 gg = goal2[r8], pp = pos2[r8];
            float dx = gg.x - pp.x, dy = gg.y - pp.y;
            d2b = sqrtf(dx * dx + dy * dy);
        }

        // ---- 32 MMAs: 4 S x 2 k-blocks x 4 n-tiles ----
        float acc[4][4] = {{0,0,0,0},{0,0,0,0},{0,0,0,0},{0,0,0,0}};
        #pragma unroll
        for (int S = 0; S < 4; S++) {
            uint32_t a0 = to_tf32(aL[S].x), a2 = to_tf32(aL[S].y);
            uint32_t a1 = to_tf32(aH[S].x), a3 = to_tf32(aH[S].y);
            #pragma unroll
            for (int nt = 0; nt < 4; nt++)
                mma_tf32(acc[nt], a0, a1, a2, a3, bf[nt][S].x, bf[nt][S].y);
            a0 = to_tf32(aL[S].z); a2 = to_tf32(aL[S].w);
            a1 = to_tf32(aH[S].z); a3 = to_tf32(aH[S].w);
            #pragma unroll
            for (int nt = 0; nt < 4; nt++)
                mma_tf32(acc[nt], a0, a1, a2, a3, bf[nt][S].z, bf[nt][S].w);
        }

        // ---- epilogue: two STG.128 per row ----
        #pragma unroll
        for (int sg = 0; sg < 2; sg++) {
            const int f4i = wq * 8 + sg * 4 + tau;     // float4 col index within row
            float4 cc = sC4[f4i];
            float4 uu = sU4[f4i];
            if (vg) {
                float4 o;
                o.x = sigmoid_fast(fmaf(d2a, uu.x, acc[2*sg][0]   + cc.x));
                o.y = sigmoid_fast(fmaf(d2a, uu.y, acc[2*sg][1]   + cc.y));
                o.z = sigmoid_fast(fmaf(d2a, uu.z, acc[2*sg+1][0] + cc.z));
                o.w = sigmoid_fast(fmaf(d2a, uu.w, acc[2*sg+1][1] + cc.w));
                if (rg == idx) o = h4[(size_t)rg * 16 + f4i];
                out4[(size_t)rg * 16 + f4i] = o;
            }
            if (v8) {
                float4 o;
                o.x = sigmoid_fast(fmaf(d2b, uu.x, acc[2*sg][2]   + cc.x));
                o.y = sigmoid_fast(fmaf(d2b, uu.y, acc[2*sg][3]   + cc.y));
                o.z = sigmoid_fast(fmaf(d2b, uu.z, acc[2*sg+1][2] + cc.z));
                o.w = sigmoid_fast(fmaf(d2b, uu.w, acc[2*sg+1][3] + cc.w));
                if (r8 == idx) o = h4[(size_t)r8 * 16 + f4i];
                out4[(size_t)r8 * 16 + f4i] = o;
            }
        }
    }
}

// ---------------- launch ----------------

extern "C" void kernel_launch(void* const* d_in, const int* in_sizes, int n_in,
                              void* d_out, int out_size)
{
    const float* h    = (const float*)d_in[0];  // (N, 64)
    const float* ghs  = (const float*)d_in[1];  // (64,)
    const float* goal = (const float*)d_in[2];  // (N, 2)
    const float* pos  = (const float*)d_in[3];  // (N, 2)
    const float* Wemb = (const float*)d_in[4];  // (32, 2)
    const float* bemb = (const float*)d_in[5];  // (32,)
    const float* Wfc  = (const float*)d_in[6];  // (64, 192)
    const float* bfc  = (const float*)d_in[7];  // (64,)
    const int*   idx  = (const int*)d_in[8];    // scalar
    float* out = (float*)d_out;                 // N*64 h_out then 64 goal_out

    int n = in_sizes[0] / HDIM;
    int nch = (n + 63) / 64;
    int grid = 296;                              // 148 SMs x 2 CTAs (persistent)
    if (grid > nch) grid = nch;

    gate_kernel<<<grid, 256>>>(h, ghs, goal, pos, Wemb, bemb, Wfc, bfc, idx, out, n);
}

// round 7
// speedup vs baseline: 4.3692x; 1.0195x over previous
#include <cuda_runtime.h>
#include <cstdint>

#define HDIM 64
#define DDIM 32

__device__ __forceinline__ float sigmoid_fast(float z) {
    float e, r;
    asm("ex2.approx.f32 %0, %1;" : "=f"(e) : "f"(z * -1.44269504088896340736f));
    asm("rcp.approx.f32 %0, %1;" : "=f"(r) : "f"(1.0f + e));
    return r;
}

__device__ __forceinline__ uint32_t to_tf32(float x) {
    uint32_t r;
    asm("cvt.rna.tf32.f32 %0, %1;" : "=r"(r) : "f"(x));
    return r;
}

__device__ __forceinline__ void mma_tf32(float* c, uint32_t a0, uint32_t a1,
                                         uint32_t a2, uint32_t a3,
                                         uint32_t b0, uint32_t b1) {
    asm volatile(
        "mma.sync.aligned.m16n8k8.row.col.f32.tf32.tf32.f32 "
        "{%0,%1,%2,%3}, {%4,%5,%6,%7}, {%8,%9}, {%0,%1,%2,%3};"
        : "+f"(c[0]), "+f"(c[1]), "+f"(c[2]), "+f"(c[3])
        : "r"(a0), "r"(a1), "r"(a2), "r"(a3), "r"(b0), "r"(b1));
}

// ---------------------------------------------------------------------------
// Single fused kernel, 3 CTAs/SM.
// out[r] = sigmoid(W2 @ h[r] + d2[r]*u2 + c),  d2[r] = ||goal[r]-position[r]||,
// row idx passed through; goal_out written by CTA 0.
//
// K-permutation (same perm on A cols and B k-rows; exact):
//   phys k = 16S + 4*tau + e  <->  frag (s = 2S+(e>>1), kappa = tau+4(e&1))
// N-permutation: phys J = wq*32 + sg*16 + 4*tau + e <-> (nt=2sg+(e>>1), 2tau+(e&1))
// => every A load LDG.128, every store STG.128.
// B kept pre-converted in smem (lane-strided uint4 -> conflict-free LDS.128),
// A fed to MMA as raw fp32 bits (HW truncates to tf32).
// ---------------------------------------------------------------------------

__global__ __launch_bounds__(256, 3)
void gate_kernel(const float* __restrict__ h,
                 const float* __restrict__ ghs,
                 const float* __restrict__ goal,
                 const float* __restrict__ position,
                 const float* __restrict__ W_emb,
                 const float* __restrict__ b_emb,
                 const float* __restrict__ W_fc,
                 const float* __restrict__ b_fc,
                 const int* __restrict__ idx_ptr,
                 float* __restrict__ out, int n)
{
    __shared__ __align__(16) uint4 sB[1024];   // [(wq*16 + nt*4 + S)*32 + lane]
    __shared__ __align__(16) float sC[HDIM];
    __shared__ __align__(16) float sU[HDIM];

    const int t = threadIdx.x;
    const int idx = idx_ptr[0];
    const int w    = t >> 5;
    const int lane = t & 31;
    const int g    = lane >> 2;      // 0..7
    const int tau  = lane & 3;       // 0..3
    const int rgrp = w >> 1;         // 0..3 : 16-row group within 64-row chunk
    const int wq   = w & 1;          // 0..1 : 32-col half

    // ---- per-CTA precompute of c[j], u2[j] (threads 0..63) ----
    if (t < HDIM) {
        const int j = t;
        const float* Wj = W_fc + j * 192;
        const float* hi = h + (size_t)idx * HDIM;
        float c0 = 0.f;
        #pragma unroll 8
        for (int k = 0; k < HDIM; k++) c0 += Wj[k] * hi[k];
        float u1 = 0.f, u2 = 0.f, cb = 0.f;
        #pragma unroll 8
        for (int d = 0; d < DDIM; d++) {
            float ws = W_emb[2 * d] + W_emb[2 * d + 1];
            u1 += Wj[128 + d] * ws;
            u2 += Wj[160 + d] * ws;
            cb += (Wj[128 + d] + Wj[160 + d]) * b_emb[d];
        }
        float c = c0 + b_fc[j] + cb;
        sC[j] = c;
        sU[j] = u2;

        if (blockIdx.x == 0) {
            float wg = 0.f;
            #pragma unroll 8
            for (int k = 0; k < HDIM; k++) wg += Wj[64 + k] * ghs[k];
            float px = position[2 * idx], py = position[2 * idx + 1];
            float gx = goal[2 * idx],     gy = goal[2 * idx + 1];
            float ddx = px - gx, ddy = py - gy;
            float dgn = sqrtf(ddx * ddx + ddy * ddy);
            float zg = c + wg + dgn * (u1 + u2);
            out[(size_t)n * HDIM + j] = 1.0f / (1.0f + expf(-zg));
        }
    }

    // ---- B fragments -> smem (warps 0,1; wq = w), tf32-converted ----
    if (w < 2) {
        #pragma unroll
        for (int nt = 0; nt < 4; nt++) {
            int j = w * 32 + (nt >> 1) * 16 + 4 * (g >> 1) + 2 * (nt & 1) + (g & 1);
            const float* Wrow = W_fc + (size_t)j * 192 + 64 + 4 * tau;
            #pragma unroll
            for (int S = 0; S < 4; S++) {
                float4 bv = *(const float4*)(Wrow + 16 * S);
                uint4 bb;
                bb.x = to_tf32(bv.x); bb.y = to_tf32(bv.y);
                bb.z = to_tf32(bv.z); bb.w = to_tf32(bv.w);
                sB[(w * 16 + nt * 4 + S) * 32 + lane] = bb;
            }
        }
    }
    __syncthreads();

    const float2* goal2 = (const float2*)goal;
    const float2* pos2  = (const float2*)position;
    const float4* h4    = (const float4*)h;
    float4* out4        = (float4*)out;
    const float4* sC4   = (const float4*)sC;
    const float4* sU4   = (const float4*)sU;
    const uint4*  sBp   = sB + wq * 512 + lane;   // + (nt*4+S)*32

    // contiguous chunk range per CTA (64 rows per chunk)
    const int nch = (n + 63) >> 6;
    const int per = (nch + gridDim.x - 1) / gridDim.x;
    const int cA = blockIdx.x * per;
    int cB = cA + per; if (cB > nch) cB = nch;
    if (cA >= cB) return;

    int rg = cA * 64 + rgrp * 16 + g;
    const float4* hgp = h4 + (size_t)rg * 16 + tau;   // row rg, float4 col tau
    const float2* gp  = goal2 + rg;
    const float2* pp  = pos2 + rg;
    float4* op        = out4 + (size_t)rg * 16;

    const float4 z4 = make_float4(0.f, 0.f, 0.f, 0.f);

    for (int ch = cA; ch < cB; ch++) {
        const bool vg = rg < n, v8 = (rg + 8) < n;

        // ---- A loads: 8x LDG.128, front-batched ----
        float4 aL[4], aH[4];
        #pragma unroll
        for (int S = 0; S < 4; S++) aL[S] = vg ? hgp[4 * S] : z4;
        #pragma unroll
        for (int S = 0; S < 4; S++) aH[S] = v8 ? hgp[128 + 4 * S] : z4;

        float d2a = 0.f, d2b = 0.f;
        if (vg) {
            float2 gg = gp[0], qq = pp[0];
            float dx = gg.x - qq.x, dy = gg.y - qq.y;
            d2a = sqrtf(dx * dx + dy * dy);
        }
        if (v8) {
            float2 gg = gp[8], qq = pp[8];
            float dx = gg.x - qq.x, dy = gg.y - qq.y;
            d2b = sqrtf(dx * dx + dy * dy);
        }

        // ---- 32 MMAs: 4 S x 2 k-blocks x 4 n-tiles; B from smem ----
        float acc[4][4] = {{0,0,0,0},{0,0,0,0},{0,0,0,0},{0,0,0,0}};
        #pragma unroll
        for (int S = 0; S < 4; S++) {
            uint4 b0 = sBp[(0 * 4 + S) * 32];
            uint4 b1 = sBp[(1 * 4 + S) * 32];
            uint4 b2 = sBp[(2 * 4 + S) * 32];
            uint4 b3 = sBp[(3 * 4 + S) * 32];
            uint32_t a0 = __float_as_uint(aL[S].x), a2 = __float_as_uint(aL[S].y);
            uint32_t a1 = __float_as_uint(aH[S].x), a3 = __float_as_uint(aH[S].y);
            mma_tf32(acc[0], a0, a1, a2, a3, b0.x, b0.y);
            mma_tf32(acc[1], a0, a1, a2, a3, b1.x, b1.y);
            mma_tf32(acc[2], a0, a1, a2, a3, b2.x, b2.y);
            mma_tf32(acc[3], a0, a1, a2, a3, b3.x, b3.y);
            a0 = __float_as_uint(aL[S].z); a2 = __float_as_uint(aL[S].w);
            a1 = __float_as_uint(aH[S].z); a3 = __float_as_uint(aH[S].w);
            mma_tf32(acc[0], a0, a1, a2, a3, b0.z, b0.w);
            mma_tf32(acc[1], a0, a1, a2, a3, b1.z, b1.w);
            mma_tf32(acc[2], a0, a1, a2, a3, b2.z, b2.w);
            mma_tf32(acc[3], a0, a1, a2, a3, b3.z, b3.w);
        }

        // ---- epilogue: two STG.128 per row ----
        #pragma unroll
        for (int sg = 0; sg < 2; sg++) {
            const int f4i = wq * 8 + sg * 4 + tau;
            float4 cc = sC4[f4i];
            float4 uu = sU4[f4i];
            if (vg) {
                float4 o;
                o.x = sigmoid_fast(fmaf(d2a, uu.x, acc[2*sg][0]   + cc.x));
                o.y = sigmoid_fast(fmaf(d2a, uu.y, acc[2*sg][1]   + cc.y));
                o.z = sigmoid_fast(fmaf(d2a, uu.z, acc[2*sg+1][0] + cc.z));
                o.w = sigmoid_fast(fmaf(d2a, uu.w, acc[2*sg+1][1] + cc.w));
                if (rg == idx) o = (hgp - tau)[f4i];
                op[f4i] = o;
            }
            if (v8) {
                float4 o;
                o.x = sigmoid_fast(fmaf(d2b, uu.x, acc[2*sg][2]   + cc.x));
                o.y = sigmoid_fast(fmaf(d2b, uu.y, acc[2*sg][3]   + cc.y));
                o.z = sigmoid_fast(fmaf(d2b, uu.z, acc[2*sg+1][2] + cc.z));
                o.w = sigmoid_fast(fmaf(d2b, uu.w, acc[2*sg+1][3] + cc.w));
                if (rg + 8 == idx) o = (hgp - tau + 128)[f4i];
                op[128 + f4i] = o;
            }
        }

        rg  += 64;
        hgp += 1024;    // 64 rows * 16 float4
        gp  += 64;
        pp  += 64;
        op  += 1024;
    }
}

// ---------------- launch ----------------

extern "C" void kernel_launch(void* const* d_in, const int* in_sizes, int n_in,
                              void* d_out, int out_size)
{
    const float* h    = (const float*)d_in[0];  // (N, 64)
    const float* ghs  = (const float*)d_in[1];  // (64,)
    const float* goal = (const float*)d_in[2];  // (N, 2)
    const float* pos  = (const float*)d_in[3];  // (N, 2)
    const float* Wemb = (const float*)d_in[4];  // (32, 2)
    const float* bemb = (const float*)d_in[5];  // (32,)
    const float* Wfc  = (const float*)d_in[6];  // (64, 192)
    const float* bfc  = (const float*)d_in[7];  // (64,)
    const int*   idx  = (const int*)d_in[8];    // scalar
    float* out = (float*)d_out;                 // N*64 h_out then 64 goal_out

    int n = in_sizes[0] / HDIM;
    int nch = (n + 63) / 64;
    int grid = 444;                              // 148 SMs x 3 CTAs (persistent)
    if (grid > nch) grid = nch;

    gate_kernel<<<grid, 256>>>(h, ghs, goal, pos, Wemb, bemb, Wfc, bfc, idx, out, n);
}

// round 9
// speedup vs baseline: 4.9472x; 1.1323x over previous
#include <cuda_runtime.h>
#include <cuda_fp16.h>
#include <cstdint>

#define HDIM 64
#define DDIM 32

__device__ __forceinline__ float sigmoid_fast(float z) {
    float e, r;
    asm("ex2.approx.f32 %0, %1;" : "=f"(e) : "f"(z * -1.44269504088896340736f));
    asm("rcp.approx.f32 %0, %1;" : "=f"(r) : "f"(1.0f + e));
    return r;
}

// pack two fp32 into half2 {lo, hi} (cvt first source -> upper half)
__device__ __forceinline__ uint32_t pack_h2(float lo, float hi) {
    uint32_t d;
    asm("cvt.rn.f16x2.f32 %0, %1, %2;" : "=r"(d) : "f"(hi), "f"(lo));
    return d;
}

__device__ __forceinline__ void mma_f16(float* c, uint32_t a0, uint32_t a1,
                                        uint32_t a2, uint32_t a3,
                                        uint32_t b0, uint32_t b1) {
    asm volatile(
        "mma.sync.aligned.m16n8k16.row.col.f32.f16.f16.f32 "
        "{%0,%1,%2,%3}, {%4,%5,%6,%7}, {%8,%9}, {%0,%1,%2,%3};"
        : "+f"(c[0]), "+f"(c[1]), "+f"(c[2]), "+f"(c[3])
        : "r"(a0), "r"(a1), "r"(a2), "r"(a3), "r"(b0), "r"(b1));
}

// ---------------------------------------------------------------------------
// Single fused kernel, 3 CTAs/SM, fp16 MMA (m16n8k16), B resident in registers.
// out[r] = sigmoid(W2 @ h[r] + d2[r]*u2 + c),  d2[r] = ||goal[r]-position[r]||,
// row idx passed through; goal_out written by CTA 0.
//
// K-permutation (same perm on A cols and B k-rows; exact):
//   frag k16-slice S, cols {2tau,2tau+1,2tau+8,2tau+9} <-> phys {16S+4tau .. +3}
//   => A fragment a0/a2 (and B b0/b1) come straight from one float4 load.
// N-permutation: phys J = wq*32+sg*16+4*tau+e <-> (nt=2sg+(e>>1), 2tau+(e&1))
//   => every store is STG.128; epilogue constants are float4 reads.
// Warp w of 8: rgrp = w>>1 (16-row group of 64-row chunk), wq = w&1 (32-col half).
// B frags: 4 nt x 4 S x uint2 = 32 regs, loaded/converted ONCE per kernel.
// ---------------------------------------------------------------------------

__global__ __launch_bounds__(256, 3)
void gate_kernel(const float* __restrict__ h,
                 const float* __restrict__ ghs,
                 const float* __restrict__ goal,
                 const float* __restrict__ position,
                 const float* __restrict__ W_emb,
                 const float* __restrict__ b_emb,
                 const float* __restrict__ W_fc,
                 const float* __restrict__ b_fc,
                 const int* __restrict__ idx_ptr,
                 float* __restrict__ out, int n)
{
    __shared__ __align__(16) float sC[HDIM];
    __shared__ __align__(16) float sU[HDIM];

    const int t = threadIdx.x;
    const int idx = idx_ptr[0];
    const int w    = t >> 5;
    const int lane = t & 31;
    const int g    = lane >> 2;      // 0..7
    const int tau  = lane & 3;       // 0..3
    const int rgrp = w >> 1;         // 0..3 : 16-row group within 64-row chunk
    const int wq   = w & 1;          // 0..1 : 32-col half

    // ---- per-CTA precompute of c[j], u2[j] (threads 0..63) ----
    if (t < HDIM) {
        const int j = t;
        const float* Wj = W_fc + j * 192;
        const float* hi = h + (size_t)idx * HDIM;
        float c0 = 0.f;
        #pragma unroll 8
        for (int k = 0; k < HDIM; k++) c0 += Wj[k] * hi[k];
        float u1 = 0.f, u2 = 0.f, cb = 0.f;
        #pragma unroll 8
        for (int d = 0; d < DDIM; d++) {
            float ws = W_emb[2 * d] + W_emb[2 * d + 1];
            u1 += Wj[128 + d] * ws;
            u2 += Wj[160 + d] * ws;
            cb += (Wj[128 + d] + Wj[160 + d]) * b_emb[d];
        }
        float c = c0 + b_fc[j] + cb;
        sC[j] = c;
        sU[j] = u2;

        if (blockIdx.x == 0) {
            float wg = 0.f;
            #pragma unroll 8
            for (int k = 0; k < HDIM; k++) wg += Wj[64 + k] * ghs[k];
            float px = position[2 * idx], py = position[2 * idx + 1];
            float gx = goal[2 * idx],     gy = goal[2 * idx + 1];
            float ddx = px - gx, ddy = py - gy;
            float dgn = sqrtf(ddx * ddx + ddy * ddy);
            float zg = c + wg + dgn * (u1 + u2);
            out[(size_t)n * HDIM + j] = 1.0f / (1.0f + expf(-zg));
        }
    }

    // ---- B fragments -> registers (per warp, once), fp16 ----
    // bf[nt][S] = (b0, b1): b0 = phys cols (16S+4tau, +1), b1 = (+2, +3) of row j
    uint2 bf[4][4];
    #pragma unroll
    for (int nt = 0; nt < 4; nt++) {
        int j = wq * 32 + (nt >> 1) * 16 + 4 * (g >> 1) + 2 * (nt & 1) + (g & 1);
        const float* Wrow = W_fc + (size_t)j * 192 + 64 + 4 * tau;
        #pragma unroll
        for (int S = 0; S < 4; S++) {
            float4 bv = *(const float4*)(Wrow + 16 * S);
            bf[nt][S].x = pack_h2(bv.x, bv.y);
            bf[nt][S].y = pack_h2(bv.z, bv.w);
        }
    }
    __syncthreads();

    const float2* goal2 = (const float2*)goal;
    const float2* pos2  = (const float2*)position;
    const float4* h4    = (const float4*)h;
    float4* out4        = (float4*)out;
    const float4* sC4   = (const float4*)sC;
    const float4* sU4   = (const float4*)sU;

    // chunk partition: full 64-row chunks fast-path; single tail chunk predicated
    const int nfull = n >> 6;
    const int nch = nfull + ((n & 63) ? 1 : 0);
    const int per = (nch + gridDim.x - 1) / gridDim.x;
    const int cA = blockIdx.x * per;
    int cB = cA + per; if (cB > nch) cB = nch;
    if (cA >= cB) return;

    int rg = cA * 64 + rgrp * 16 + g;
    const float4* hgp = h4 + (size_t)rg * 16 + tau;   // row rg, float4 col tau
    const float2* gp  = goal2 + rg;
    const float2* pp  = pos2 + rg;
    float4* op        = out4 + (size_t)rg * 16;

    for (int ch = cA; ch < cB; ch++) {
        const bool fullc = (ch < nfull);
        const bool vg = fullc || (rg < n);
        const bool v8 = fullc || (rg + 8 < n);
        const float4 z4 = make_float4(0.f, 0.f, 0.f, 0.f);

        // ---- A loads: 8x LDG.128, front-batched ----
        float4 aL[4], aH[4];
        if (fullc) {
            #pragma unroll
            for (int S = 0; S < 4; S++) aL[S] = hgp[4 * S];
            #pragma unroll
            for (int S = 0; S < 4; S++) aH[S] = hgp[128 + 4 * S];
        } else {
            #pragma unroll
            for (int S = 0; S < 4; S++) aL[S] = vg ? hgp[4 * S] : z4;
            #pragma unroll
            for (int S = 0; S < 4; S++) aH[S] = v8 ? hgp[128 + 4 * S] : z4;
        }

        float d2a = 0.f, d2b = 0.f;
        if (vg) {
            float2 gg = gp[0], qq = pp[0];
            float dx = gg.x - qq.x, dy = gg.y - qq.y;
            d2a = sqrtf(dx * dx + dy * dy);
        }
        if (v8) {
            float2 gg = gp[8], qq = pp[8];
            float dx = gg.x - qq.x, dy = gg.y - qq.y;
            d2b = sqrtf(dx * dx + dy * dy);
        }

        // ---- convert A to fp16 fragments ----
        uint32_t a0[4], a1[4], a2[4], a3[4];
        #pragma unroll
        for (int S = 0; S < 4; S++) {
            a0[S] = pack_h2(aL[S].x, aL[S].y);
            a2[S] = pack_h2(aL[S].z, aL[S].w);
            a1[S] = pack_h2(aH[S].x, aH[S].y);
            a3[S] = pack_h2(aH[S].z, aH[S].w);
        }

        // ---- 16 MMAs: 4 S x 4 n-tiles, all operands in registers ----
        float acc[4][4] = {{0,0,0,0},{0,0,0,0},{0,0,0,0},{0,0,0,0}};
        #pragma unroll
        for (int S = 0; S < 4; S++) {
            mma_f16(acc[0], a0[S], a1[S], a2[S], a3[S], bf[0][S].x, bf[0][S].y);
            mma_f16(acc[1], a0[S], a1[S], a2[S], a3[S], bf[1][S].x, bf[1][S].y);
            mma_f16(acc[2], a0[S], a1[S], a2[S], a3[S], bf[2][S].x, bf[2][S].y);
            mma_f16(acc[3], a0[S], a1[S], a2[S], a3[S], bf[3][S].x, bf[3][S].y);
        }

        // ---- epilogue: two STG.128 per row ----
        #pragma unroll
        for (int sg = 0; sg < 2; sg++) {
            const int f4i = wq * 8 + sg * 4 + tau;
            float4 cc = sC4[f4i];
            float4 uu = sU4[f4i];
            if (vg) {
                float4 o;
                o.x = sigmoid_fast(fmaf(d2a, uu.x, acc[2*sg][0]   + cc.x));
                o.y = sigmoid_fast(fmaf(d2a, uu.y, acc[2*sg][1]   + cc.y));
                o.z = sigmoid_fast(fmaf(d2a, uu.z, acc[2*sg+1][0] + cc.z));
                o.w = sigmoid_fast(fmaf(d2a, uu.w, acc[2*sg+1][1] + cc.w));
                if (rg == idx) o = (hgp - tau)[f4i];
                op[f4i] = o;
            }
            if (v8) {
                float4 o;
                o.x = sigmoid_fast(fmaf(d2b, uu.x, acc[2*sg][2]   + cc.x));
                o.y = sigmoid_fast(fmaf(d2b, uu.y, acc[2*sg][3]   + cc.y));
                o.z = sigmoid_fast(fmaf(d2b, uu.z, acc[2*sg+1][2] + cc.z));
                o.w = sigmoid_fast(fmaf(d2b, uu.w, acc[2*sg+1][3] + cc.w));
                if (rg + 8 == idx) o = (hgp - tau + 128)[f4i];
                op[128 + f4i] = o;
            }
        }

        rg  += 64;
        hgp += 1024;    // 64 rows * 16 float4
        gp  += 64;
        pp  += 64;
        op  += 1024;
    }
}

// ---------------- launch ----------------

extern "C" void kernel_launch(void* const* d_in, const int* in_sizes, int n_in,
                              void* d_out, int out_size)
{
    const float* h    = (const float*)d_in[0];  // (N, 64)
    const float* ghs  = (const float*)d_in[1];  // (64,)
    const float* goal = (const float*)d_in[2];  // (N, 2)
    const float* pos  = (const float*)d_in[3];  // (N, 2)
    const float* Wemb = (const float*)d_in[4];  // (32, 2)
    const float* bemb = (const float*)d_in[5];  // (32,)
    const float* Wfc  = (const float*)d_in[6];  // (64, 192)
    const float* bfc  = (const float*)d_in[7];  // (64,)
    const int*   idx  = (const int*)d_in[8];    // scalar
    float* out = (float*)d_out;                 // N*64 h_out then 64 goal_out

    int n = in_sizes[0] / HDIM;
    int nch = (n + 63) / 64;
    int grid = 444;                              // 148 SMs x 3 CTAs (persistent)
    if (grid > nch) grid = nch;

    gate_kernel<<<grid, 256>>>(h, ghs, goal, pos, Wemb, bemb, Wfc, bfc, idx, out, n);
}

// round 11
// speedup vs baseline: 5.2155x; 1.0542x over previous
#include <cuda_runtime.h>
#include <cuda_fp16.h>
#include <cstdint>

#define HDIM 64
#define DDIM 32

__device__ __forceinline__ float sigmoid_fast(float z) {
    float e, r;
    asm("ex2.approx.f32 %0, %1;" : "=f"(e) : "f"(z * -1.44269504088896340736f));
    asm("rcp.approx.f32 %0, %1;" : "=f"(r) : "f"(1.0f + e));
    return r;
}

// pack two fp32 into half2 {lo, hi}
__device__ __forceinline__ uint32_t pack_h2(float lo, float hi) {
    uint32_t d;
    asm("cvt.rn.f16x2.f32 %0, %1, %2;" : "=r"(d) : "f"(hi), "f"(lo));
    return d;
}

__device__ __forceinline__ void mma_f16(float* c, uint32_t a0, uint32_t a1,
                                        uint32_t a2, uint32_t a3,
                                        uint32_t b0, uint32_t b1) {
    asm volatile(
        "mma.sync.aligned.m16n8k16.row.col.f32.f16.f16.f32 "
        "{%0,%1,%2,%3}, {%4,%5,%6,%7}, {%8,%9}, {%0,%1,%2,%3};"
        : "+f"(c[0]), "+f"(c[1]), "+f"(c[2]), "+f"(c[3])
        : "r"(a0), "r"(a1), "r"(a2), "r"(a3), "r"(b0), "r"(b1));
}

// ---------------------------------------------------------------------------
// Single fused kernel, fp16 MMA (m16n8k16), FULL B resident in registers
// (8 n-tiles x 4 S x uint2 = 64 regs) -- each warp owns 16 rows x all 64 cols,
// so no warp duplicates another warp's A loads (halves L1 wavefronts for A).
// 2 CTAs/SM, 8 warps, chunk = 128 rows per CTA iteration.
//
// out[r] = sigmoid(W2 @ h[r] + d2[r]*u2 + c),  d2[r] = ||goal[r]-position[r]||,
// row idx passed through; goal_out written by CTA 0.
//
// K-permutation (same perm on A cols and B k-rows; exact):
//   frag k16-slice S <-> phys cols {16S+4tau .. 16S+4tau+3} per lane
// N-permutation: phys J = sgg*16 + 4*tau + e <-> (nt = 2*sgg + (e>>1), 2tau+(e&1))
//   => every load LDG.128, every store STG.128, constants via float4.
// ---------------------------------------------------------------------------

__global__ __launch_bounds__(256, 2)
void gate_kernel(const float* __restrict__ h,
                 const float* __restrict__ ghs,
                 const float* __restrict__ goal,
                 const float* __restrict__ position,
                 const float* __restrict__ W_emb,
                 const float* __restrict__ b_emb,
                 const float* __restrict__ W_fc,
                 const float* __restrict__ b_fc,
                 const int* __restrict__ idx_ptr,
                 float* __restrict__ out, int n)
{
    __shared__ __align__(16) float sC[HDIM];
    __shared__ __align__(16) float sU[HDIM];

    const int t = threadIdx.x;
    const int idx = idx_ptr[0];
    const int w    = t >> 5;         // 0..7 : 16-row group within 128-row chunk
    const int lane = t & 31;
    const int g    = lane >> 2;      // 0..7
    const int tau  = lane & 3;       // 0..3

    // ---- per-CTA precompute of c[j], u2[j] (threads 0..63) ----
    if (t < HDIM) {
        const int j = t;
        const float* Wj = W_fc + j * 192;
        const float* hi = h + (size_t)idx * HDIM;
        float c0 = 0.f;
        #pragma unroll 8
        for (int k = 0; k < HDIM; k++) c0 += Wj[k] * hi[k];
        float u1 = 0.f, u2 = 0.f, cb = 0.f;
        #pragma unroll 8
        for (int d = 0; d < DDIM; d++) {
            float ws = W_emb[2 * d] + W_emb[2 * d + 1];
            u1 += Wj[128 + d] * ws;
            u2 += Wj[160 + d] * ws;
            cb += (Wj[128 + d] + Wj[160 + d]) * b_emb[d];
        }
        float c = c0 + b_fc[j] + cb;
        sC[j] = c;
        sU[j] = u2;

        if (blockIdx.x == 0) {
            float wg = 0.f;
            #pragma unroll 8
            for (int k = 0; k < HDIM; k++) wg += Wj[64 + k] * ghs[k];
            float px = position[2 * idx], py = position[2 * idx + 1];
            float gx = goal[2 * idx],     gy = goal[2 * idx + 1];
            float ddx = px - gx, ddy = py - gy;
            float dgn = sqrtf(ddx * ddx + ddy * ddy);
            float zg = c + wg + dgn * (u1 + u2);
            out[(size_t)n * HDIM + j] = 1.0f / (1.0f + expf(-zg));
        }
    }

    // ---- FULL B -> registers (per warp, once), fp16: 64 regs ----
    // bf[nt][S]: b0 = phys cols (16S+4tau, +1), b1 = (+2, +3) of row j(nt,g)
    uint2 bf[8][4];
    #pragma unroll
    for (int nt = 0; nt < 8; nt++) {
        int j = (nt >> 1) * 16 + 4 * (g >> 1) + 2 * (nt & 1) + (g & 1);
        const float* Wrow = W_fc + (size_t)j * 192 + 64 + 4 * tau;
        #pragma unroll
        for (int S = 0; S < 4; S++) {
            float4 bv = *(const float4*)(Wrow + 16 * S);
            bf[nt][S].x = pack_h2(bv.x, bv.y);
            bf[nt][S].y = pack_h2(bv.z, bv.w);
        }
    }
    __syncthreads();

    const float2* goal2 = (const float2*)goal;
    const float2* pos2  = (const float2*)position;
    const float4* h4    = (const float4*)h;
    float4* out4        = (float4*)out;
    const float4* sC4   = (const float4*)sC;
    const float4* sU4   = (const float4*)sU;

    // chunk partition: 128 rows per chunk; full chunks fast-path, tail predicated
    const int nfull = n >> 7;
    const int nch = nfull + ((n & 127) ? 1 : 0);
    const int per = (nch + gridDim.x - 1) / gridDim.x;
    const int cA = blockIdx.x * per;
    int cB = cA + per; if (cB > nch) cB = nch;
    if (cA >= cB) return;

    int rg = cA * 128 + w * 16 + g;
    const float4* hgp = h4 + (size_t)rg * 16 + tau;   // row rg, float4 col tau
    const float2* gp  = goal2 + rg;
    const float2* pp  = pos2 + rg;
    float4* op        = out4 + (size_t)rg * 16;

    for (int ch = cA; ch < cB; ch++) {
        const bool fullc = (ch < nfull);
        const bool vg = fullc || (rg < n);
        const bool v8 = fullc || (rg + 8 < n);
        const float4 z4 = make_float4(0.f, 0.f, 0.f, 0.f);

        // ---- A loads: 8x LDG.128, front-batched (rows rg, rg+8) ----
        float4 aL[4], aH[4];
        if (fullc) {
            #pragma unroll
            for (int S = 0; S < 4; S++) aL[S] = hgp[4 * S];
            #pragma unroll
            for (int S = 0; S < 4; S++) aH[S] = hgp[128 + 4 * S];
        } else {
            #pragma unroll
            for (int S = 0; S < 4; S++) aL[S] = vg ? hgp[4 * S] : z4;
            #pragma unroll
            for (int S = 0; S < 4; S++) aH[S] = v8 ? hgp[128 + 4 * S] : z4;
        }

        float d2a = 0.f, d2b = 0.f;
        if (vg) {
            float2 gg = gp[0], qq = pp[0];
            float dx = gg.x - qq.x, dy = gg.y - qq.y;
            d2a = sqrtf(dx * dx + dy * dy);
        }
        if (v8) {
            float2 gg = gp[8], qq = pp[8];
            float dx = gg.x - qq.x, dy = gg.y - qq.y;
            d2b = sqrtf(dx * dx + dy * dy);
        }

        // ---- convert A to fp16 fragments ----
        uint32_t a0[4], a1[4], a2[4], a3[4];
        #pragma unroll
        for (int S = 0; S < 4; S++) {
            a0[S] = pack_h2(aL[S].x, aL[S].y);
            a2[S] = pack_h2(aL[S].z, aL[S].w);
            a1[S] = pack_h2(aH[S].x, aH[S].y);
            a3[S] = pack_h2(aH[S].z, aH[S].w);
        }

        // ---- 32 MMAs: 4 S x 8 n-tiles, all operands in registers ----
        float acc[8][4] = {{0,0,0,0},{0,0,0,0},{0,0,0,0},{0,0,0,0},
                           {0,0,0,0},{0,0,0,0},{0,0,0,0},{0,0,0,0}};
        #pragma unroll
        for (int S = 0; S < 4; S++) {
            #pragma unroll
            for (int nt = 0; nt < 8; nt++)
                mma_f16(acc[nt], a0[S], a1[S], a2[S], a3[S], bf[nt][S].x, bf[nt][S].y);
        }

        // ---- epilogue: four STG.128 per row ----
        #pragma unroll
        for (int sgg = 0; sgg < 4; sgg++) {
            const int f4i = sgg * 4 + tau;
            float4 cc = sC4[f4i];
            float4 uu = sU4[f4i];
            if (vg) {
                float4 o;
                o.x = sigmoid_fast(fmaf(d2a, uu.x, acc[2*sgg][0]   + cc.x));
                o.y = sigmoid_fast(fmaf(d2a, uu.y, acc[2*sgg][1]   + cc.y));
                o.z = sigmoid_fast(fmaf(d2a, uu.z, acc[2*sgg+1][0] + cc.z));
                o.w = sigmoid_fast(fmaf(d2a, uu.w, acc[2*sgg+1][1] + cc.w));
                if (rg == idx) o = (hgp - tau)[f4i];
                op[f4i] = o;
            }
            if (v8) {
                float4 o;
                o.x = sigmoid_fast(fmaf(d2b, uu.x, acc[2*sgg][2]   + cc.x));
                o.y = sigmoid_fast(fmaf(d2b, uu.y, acc[2*sgg][3]   + cc.y));
                o.z = sigmoid_fast(fmaf(d2b, uu.z, acc[2*sgg+1][2] + cc.z));
                o.w = sigmoid_fast(fmaf(d2b, uu.w, acc[2*sgg+1][3] + cc.w));
                if (rg + 8 == idx) o = (hgp - tau + 128)[f4i];
                op[128 + f4i] = o;
            }
        }

        rg  += 128;
        hgp += 2048;    // 128 rows * 16 float4
        gp  += 128;
        pp  += 128;
        op  += 2048;
    }
}

// ---------------- launch ----------------

extern "C" void kernel_launch(void* const* d_in, const int* in_sizes, int n_in,
                              void* d_out, int out_size)
{
    const float* h    = (const float*)d_in[0];  // (N, 64)
    const float* ghs  = (const float*)d_in[1];  // (64,)
    const float* goal = (const float*)d_in[2];  // (N, 2)
    const float* pos  = (const float*)d_in[3];  // (N, 2)
    const float* Wemb = (const float*)d_in[4];  // (32, 2)
    const float* bemb = (const float*)d_in[5];  // (32,)
    const float* Wfc  = (const float*)d_in[6];  // (64, 192)
    const float* bfc  = (const float*)d_in[7];  // (64,)
    const int*   idx  = (const int*)d_in[8];    // scalar
    float* out = (float*)d_out;                 // N*64 h_out then 64 goal_out

    int n = in_sizes[0] / HDIM;
    int nch = (n + 127) / 128;
    int grid = 296;                              // 148 SMs x 2 CTAs (persistent)
    if (grid > nch) grid = nch;

    gate_kernel<<<grid, 256>>>(h, ghs, goal, pos, Wemb, bemb, Wfc, bfc, idx, out, n);
}

// round 13
// speedup vs baseline: 5.6182x; 1.0772x over previous
#include <cuda_runtime.h>
#include <cuda_fp16.h>
#include <cstdint>

#define HDIM 64
#define DDIM 32

__device__ __forceinline__ float sigmoid_fast(float z) {
    float e, r;
    asm("ex2.approx.f32 %0, %1;" : "=f"(e) : "f"(z * -1.44269504088896340736f));
    asm("rcp.approx.f32 %0, %1;" : "=f"(r) : "f"(1.0f + e));
    return r;
}

// pack two fp32 into half2 {lo, hi}
__device__ __forceinline__ uint32_t pack_h2(float lo, float hi) {
    uint32_t d;
    asm("cvt.rn.f16x2.f32 %0, %1, %2;" : "=r"(d) : "f"(hi), "f"(lo));
    return d;
}

__device__ __forceinline__ void prefetch_l2(const void* p) {
    asm volatile("prefetch.global.L2 [%0];" :: "l"(p));
}

__device__ __forceinline__ void mma_f16(float* c, uint32_t a0, uint32_t a1,
                                        uint32_t a2, uint32_t a3,
                                        uint32_t b0, uint32_t b1) {
    asm volatile(
        "mma.sync.aligned.m16n8k16.row.col.f32.f16.f16.f32 "
        "{%0,%1,%2,%3}, {%4,%5,%6,%7}, {%8,%9}, {%0,%1,%2,%3};"
        : "+f"(c[0]), "+f"(c[1]), "+f"(c[2]), "+f"(c[3])
        : "r"(a0), "r"(a1), "r"(a2), "r"(a3), "r"(b0), "r"(b1));
}

// ---------------------------------------------------------------------------
// Single fused kernel, fp16 MMA (m16n8k16), FULL B resident in registers
// (8 n-tiles x 4 S x uint2 = 64 regs) -- each warp owns 16 rows x all 64 cols.
// 2 CTAs/SM, 8 warps, chunk = 128 rows per CTA iteration.
// R12/R13: zero-register L2 prefetch of the NEXT chunk's h/goal/pos lines
// (1 prefetch per lane covers all 32 h-lines of the warp's next 16 rows),
// converting the chunk-top LDG stall from DRAM (~600-900cyc) to L2 (~250cyc).
//
// out[r] = sigmoid(W2 @ h[r] + d2[r]*u2 + c),  d2[r] = ||goal[r]-position[r]||,
// row idx passed through; goal_out written by CTA 0.
//
// K-permutation (same perm on A cols and B k-rows; exact):
//   frag k16-slice S <-> phys cols {16S+4tau .. 16S+4tau+3} per lane
// N-permutation: phys J = sgg*16 + 4*tau + e <-> (nt = 2*sgg + (e>>1), 2tau+(e&1))
//   => every load LDG.128, every store STG.128, constants via float4.
// ---------------------------------------------------------------------------

__global__ __launch_bounds__(256, 2)
void gate_kernel(const float* __restrict__ h,
                 const float* __restrict__ ghs,
                 const float* __restrict__ goal,
                 const float* __restrict__ position,
                 const float* __restrict__ W_emb,
                 const float* __restrict__ b_emb,
                 const float* __restrict__ W_fc,
                 const float* __restrict__ b_fc,
                 const int* __restrict__ idx_ptr,
                 float* __restrict__ out, int n)
{
    __shared__ __align__(16) float sC[HDIM];
    __shared__ __align__(16) float sU[HDIM];

    const int t = threadIdx.x;
    const int idx = idx_ptr[0];
    const int w    = t >> 5;         // 0..7 : 16-row group within 128-row chunk
    const int lane = t & 31;
    const int g    = lane >> 2;      // 0..7
    const int tau  = lane & 3;       // 0..3

    // ---- per-CTA precompute of c[j], u2[j] (threads 0..63) ----
    if (t < HDIM) {
        const int j = t;
        const float* Wj = W_fc + j * 192;
        const float* hi = h + (size_t)idx * HDIM;
        float c0 = 0.f;
        #pragma unroll 8
        for (int k = 0; k < HDIM; k++) c0 += Wj[k] * hi[k];
        float u1 = 0.f, u2 = 0.f, cb = 0.f;
        #pragma unroll 8
        for (int d = 0; d < DDIM; d++) {
            float ws = W_emb[2 * d] + W_emb[2 * d + 1];
            u1 += Wj[128 + d] * ws;
            u2 += Wj[160 + d] * ws;
            cb += (Wj[128 + d] + Wj[160 + d]) * b_emb[d];
        }
        float c = c0 + b_fc[j] + cb;
        sC[j] = c;
        sU[j] = u2;

        if (blockIdx.x == 0) {
            float wg = 0.f;
            #pragma unroll 8
            for (int k = 0; k < HDIM; k++) wg += Wj[64 + k] * ghs[k];
            float px = position[2 * idx], py = position[2 * idx + 1];
            float gx = goal[2 * idx],     gy = goal[2 * idx + 1];
            float ddx = px - gx, ddy = py - gy;
            float dgn = sqrtf(ddx * ddx + ddy * ddy);
            float zg = c + wg + dgn * (u1 + u2);
            out[(size_t)n * HDIM + j] = 1.0f / (1.0f + expf(-zg));
        }
    }

    // ---- FULL B -> registers (per warp, once), fp16: 64 regs ----
    uint2 bf[8][4];
    #pragma unroll
    for (int nt = 0; nt < 8; nt++) {
        int j = (nt >> 1) * 16 + 4 * (g >> 1) + 2 * (nt & 1) + (g & 1);
        const float* Wrow = W_fc + (size_t)j * 192 + 64 + 4 * tau;
        #pragma unroll
        for (int S = 0; S < 4; S++) {
            float4 bv = *(const float4*)(Wrow + 16 * S);
            bf[nt][S].x = pack_h2(bv.x, bv.y);
            bf[nt][S].y = pack_h2(bv.z, bv.w);
        }
    }
    __syncthreads();

    const float2* goal2 = (const float2*)goal;
    const float2* pos2  = (const float2*)position;
    const float4* h4    = (const float4*)h;
    float4* out4        = (float4*)out;
    const float4* sC4   = (const float4*)sC;
    const float4* sU4   = (const float4*)sU;

    // chunk partition: 128 rows per chunk; full chunks fast-path, tail predicated
    const int nfull = n >> 7;
    const int nch = nfull + ((n & 127) ? 1 : 0);
    const int per = (nch + gridDim.x - 1) / gridDim.x;
    const int cA = blockIdx.x * per;
    int cB = cA + per; if (cB > nch) cB = nch;
    if (cA >= cB) return;

    int rg = cA * 128 + w * 16 + g;
    const float4* hgp = h4 + (size_t)rg * 16 + tau;   // row rg, float4 col tau
    const float2* gp  = goal2 + rg;
    const float2* pp  = pos2 + rg;
    float4* op        = out4 + (size_t)rg * 16;

    // prefetch base: warp's 16-row block start, next chunk. Lane l covers line
    // (row = l>>1, half = l&1): 16 rows x 2 x 128B = this warp's entire A slice.
    const char* pfb = (const char*)(hgp - tau - (size_t)g * 16) + (size_t)(lane >> 1) * 256
                      + (size_t)(lane & 1) * 128;

    for (int ch = cA; ch < cB; ch++) {
        const bool fullc = (ch < nfull);
        const bool vg = fullc || (rg < n);
        const bool v8 = fullc || (rg + 8 < n);
        const float4 z4 = make_float4(0.f, 0.f, 0.f, 0.f);

        // ---- A loads: 8x LDG.128, front-batched (rows rg, rg+8) ----
        float4 aL[4], aH[4];
        if (fullc) {
            #pragma unroll
            for (int S = 0; S < 4; S++) aL[S] = hgp[4 * S];
            #pragma unroll
            for (int S = 0; S < 4; S++) aH[S] = hgp[128 + 4 * S];
        } else {
            #pragma unroll
            for (int S = 0; S < 4; S++) aL[S] = vg ? hgp[4 * S] : z4;
            #pragma unroll
            for (int S = 0; S < 4; S++) aH[S] = v8 ? hgp[128 + 4 * S] : z4;
        }

        // ---- prefetch NEXT chunk into L2 (no regs, no scoreboard) ----
        if (ch + 1 < nfull) {
            prefetch_l2(pfb + 32768);                 // 128 rows * 256 B ahead
            if (lane == 0) prefetch_l2((const char*)(gp + 128));
            if (lane == 1) prefetch_l2((const char*)(pp + 128));
        }

        float d2a = 0.f, d2b = 0.f;
        if (vg) {
            float2 gg = gp[0], qq = pp[0];
            float dx = gg.x - qq.x, dy = gg.y - qq.y;
            d2a = sqrtf(dx * dx + dy * dy);
        }
        if (v8) {
            float2 gg = gp[8], qq = pp[8];
            float dx = gg.x - qq.x, dy = gg.y - qq.y;
            d2b = sqrtf(dx * dx + dy * dy);
        }

        // ---- convert A to fp16 fragments ----
        uint32_t a0[4], a1[4], a2[4], a3[4];
        #pragma unroll
        for (int S = 0; S < 4; S++) {
            a0[S] = pack_h2(aL[S].x, aL[S].y);
            a2[S] = pack_h2(aL[S].z, aL[S].w);
            a1[S] = pack_h2(aH[S].x, aH[S].y);
            a3[S] = pack_h2(aH[S].z, aH[S].w);
        }

        // ---- 32 MMAs: 4 S x 8 n-tiles, all operands in registers ----
        float acc[8][4] = {{0,0,0,0},{0,0,0,0},{0,0,0,0},{0,0,0,0},
                           {0,0,0,0},{0,0,0,0},{0,0,0,0},{0,0,0,0}};
        #pragma unroll
        for (int S = 0; S < 4; S++) {
            #pragma unroll
            for (int nt = 0; nt < 8; nt++)
                mma_f16(acc[nt], a0[S], a1[S], a2[S], a3[S], bf[nt][S].x, bf[nt][S].y);
        }

        // ---- epilogue: four STG.128 per row ----
        #pragma unroll
        for (int sgg = 0; sgg < 4; sgg++) {
            const int f4i = sgg * 4 + tau;
            float4 cc = sC4[f4i];
            float4 uu = sU4[f4i];
            if (vg) {
                float4 o;
                o.x = sigmoid_fast(fmaf(d2a, uu.x, acc[2*sgg][0]   + cc.x));
                o.y = sigmoid_fast(fmaf(d2a, uu.y, acc[2*sgg][1]   + cc.y));
                o.z = sigmoid_fast(fmaf(d2a, uu.z, acc[2*sgg+1][0] + cc.z));
                o.w = sigmoid_fast(fmaf(d2a, uu.w, acc[2*sgg+1][1] + cc.w));
                if (rg == idx) o = (hgp - tau)[f4i];
                op[f4i] = o;
            }
            if (v8) {
                float4 o;
                o.x = sigmoid_fast(fmaf(d2b, uu.x, acc[2*sgg][2]   + cc.x));
                o.y = sigmoid_fast(fmaf(d2b, uu.y, acc[2*sgg][3]   + cc.y));
                o.z = sigmoid_fast(fmaf(d2b, uu.z, acc[2*sgg+1][2] + cc.z));
                o.w = sigmoid_fast(fmaf(d2b, uu.w, acc[2*sgg+1][3] + cc.w));
                if (rg + 8 == idx) o = (hgp - tau + 128)[f4i];
                op[128 + f4i] = o;
            }
        }

        rg  += 128;
        hgp += 2048;    // 128 rows * 16 float4
        pfb += 32768;
        gp  += 128;
        pp  += 128;
        op  += 2048;
    }
}

// ---------------- launch ----------------

extern "C" void kernel_launch(void* const* d_in, const int* in_sizes, int n_in,
                              void* d_out, int out_size)
{
    const float* h    = (const float*)d_in[0];  // (N, 64)
    const float* ghs  = (const float*)d_in[1];  // (64,)
    const float* goal = (const float*)d_in[2];  // (N, 2)
    const float* pos  = (const float*)d_in[3];  // (N, 2)
    const float* Wemb = (const float*)d_in[4];  // (32, 2)
    const float* bemb = (const float*)d_in[5];  // (32,)
    const float* Wfc  = (const float*)d_in[6];  // (64, 192)
    const float* bfc  = (const float*)d_in[7];  // (64,)
    const int*   idx  = (const int*)d_in[8];    // scalar
    float* out = (float*)d_out;                 // N*64 h_out then 64 goal_out

    int n = in_sizes[0] / HDIM;
    int nch = (n + 127) / 128;
    int grid = 296;                              // 148 SMs x 2 CTAs (persistent)
    if (grid > nch) grid = nch;

    gate_kernel<<<grid, 256>>>(h, ghs, goal, pos, Wemb, bemb, Wfc, bfc, idx, out, n);
}

// round 14
// speedup vs baseline: 5.7257x; 1.0191x over previous
#include <cuda_runtime.h>
#include <cuda_fp16.h>
#include <cstdint>

#define HDIM 64
#define DDIM 32

__device__ __forceinline__ float sigmoid_fast(float z) {
    float e, r;
    asm("ex2.approx.f32 %0, %1;" : "=f"(e) : "f"(z * -1.44269504088896340736f));
    asm("rcp.approx.f32 %0, %1;" : "=f"(r) : "f"(1.0f + e));
    return r;
}

// pack two fp32 into half2 {lo, hi}
__device__ __forceinline__ uint32_t pack_h2(float lo, float hi) {
    uint32_t d;
    asm("cvt.rn.f16x2.f32 %0, %1, %2;" : "=r"(d) : "f"(hi), "f"(lo));
    return d;
}

__device__ __forceinline__ void prefetch_l2(const void* p) {
    asm volatile("prefetch.global.L2 [%0];" :: "l"(p));
}

__device__ __forceinline__ void mma_f16(float* c, uint32_t a0, uint32_t a1,
                                        uint32_t a2, uint32_t a3,
                                        uint32_t b0, uint32_t b1) {
    asm volatile(
        "mma.sync.aligned.m16n8k16.row.col.f32.f16.f16.f32 "
        "{%0,%1,%2,%3}, {%4,%5,%6,%7}, {%8,%9}, {%0,%1,%2,%3};"
        : "+f"(c[0]), "+f"(c[1]), "+f"(c[2]), "+f"(c[3])
        : "r"(a0), "r"(a1), "r"(a2), "r"(a3), "r"(b0), "r"(b1));
}

// ---------------------------------------------------------------------------
// Single fused kernel, fp16 MMA (m16n8k16), FULL B resident in registers
// (8 n-tiles x 4 S x uint2 = 64 regs) -- each warp owns 16 rows x all 64 cols.
// 2 CTAs/SM, 8 warps, chunk = 128 rows per CTA iteration.
// R13: zero-register L2 prefetch of next chunk's h/goal/pos (WIN: 66->61us).
// R14: streaming cache policy (__ldcs on h/goal/pos, __stcs on out) so the
// write-once output and read-once input streams don't evict prefetched lines;
// row-idx pass-through hoisted out of the hot loop into a post-loop fixup.
//
// out[r] = sigmoid(W2 @ h[r] + d2[r]*u2 + c),  d2[r] = ||goal[r]-position[r]||,
// row idx passed through; goal_out written by CTA 0.
//
// K-permutation (same perm on A cols and B k-rows; exact):
//   frag k16-slice S <-> phys cols {16S+4tau .. 16S+4tau+3} per lane
// N-permutation: phys J = sgg*16 + 4*tau + e <-> (nt = 2*sgg + (e>>1), 2tau+(e&1))
//   => every load LDG.128, every store STG.128, constants via float4.
// ---------------------------------------------------------------------------

__global__ __launch_bounds__(256, 2)
void gate_kernel(const float* __restrict__ h,
                 const float* __restrict__ ghs,
                 const float* __restrict__ goal,
                 const float* __restrict__ position,
                 const float* __restrict__ W_emb,
                 const float* __restrict__ b_emb,
                 const float* __restrict__ W_fc,
                 const float* __restrict__ b_fc,
                 const int* __restrict__ idx_ptr,
                 float* __restrict__ out, int n)
{
    __shared__ __align__(16) float sC[HDIM];
    __shared__ __align__(16) float sU[HDIM];

    const int t = threadIdx.x;
    const int idx = idx_ptr[0];
    const int w    = t >> 5;         // 0..7 : 16-row group within 128-row chunk
    const int lane = t & 31;
    const int g    = lane >> 2;      // 0..7
    const int tau  = lane & 3;       // 0..3

    // ---- per-CTA precompute of c[j], u2[j] (threads 0..63) ----
    if (t < HDIM) {
        const int j = t;
        const float* Wj = W_fc + j * 192;
        const float* hi = h + (size_t)idx * HDIM;
        float c0 = 0.f;
        #pragma unroll 8
        for (int k = 0; k < HDIM; k++) c0 += Wj[k] * hi[k];
        float u1 = 0.f, u2 = 0.f, cb = 0.f;
        #pragma unroll 8
        for (int d = 0; d < DDIM; d++) {
            float ws = W_emb[2 * d] + W_emb[2 * d + 1];
            u1 += Wj[128 + d] * ws;
            u2 += Wj[160 + d] * ws;
            cb += (Wj[128 + d] + Wj[160 + d]) * b_emb[d];
        }
        float c = c0 + b_fc[j] + cb;
        sC[j] = c;
        sU[j] = u2;

        if (blockIdx.x == 0) {
            float wg = 0.f;
            #pragma unroll 8
            for (int k = 0; k < HDIM; k++) wg += Wj[64 + k] * ghs[k];
            float px = position[2 * idx], py = position[2 * idx + 1];
            float gx = goal[2 * idx],     gy = goal[2 * idx + 1];
            float ddx = px - gx, ddy = py - gy;
            float dgn = sqrtf(ddx * ddx + ddy * ddy);
            float zg = c + wg + dgn * (u1 + u2);
            out[(size_t)n * HDIM + j] = 1.0f / (1.0f + expf(-zg));
        }
    }

    // ---- FULL B -> registers (per warp, once), fp16: 64 regs ----
    uint2 bf[8][4];
    #pragma unroll
    for (int nt = 0; nt < 8; nt++) {
        int j = (nt >> 1) * 16 + 4 * (g >> 1) + 2 * (nt & 1) + (g & 1);
        const float* Wrow = W_fc + (size_t)j * 192 + 64 + 4 * tau;
        #pragma unroll
        for (int S = 0; S < 4; S++) {
            float4 bv = *(const float4*)(Wrow + 16 * S);
            bf[nt][S].x = pack_h2(bv.x, bv.y);
            bf[nt][S].y = pack_h2(bv.z, bv.w);
        }
    }
    __syncthreads();

    const float2* goal2 = (const float2*)goal;
    const float2* pos2  = (const float2*)position;
    const float4* h4    = (const float4*)h;
    float4* out4        = (float4*)out;
    const float4* sC4   = (const float4*)sC;
    const float4* sU4   = (const float4*)sU;

    // chunk partition: 128 rows per chunk; full chunks fast-path, tail predicated
    const int nfull = n >> 7;
    const int nch = nfull + ((n & 127) ? 1 : 0);
    const int per = (nch + gridDim.x - 1) / gridDim.x;
    const int cA = blockIdx.x * per;
    int cB = cA + per; if (cB > nch) cB = nch;
    if (cA >= cB) return;

    int rg = cA * 128 + w * 16 + g;
    const float4* hgp = h4 + (size_t)rg * 16 + tau;   // row rg, float4 col tau
    const float2* gp  = goal2 + rg;
    const float2* pp  = pos2 + rg;
    float4* op        = out4 + (size_t)rg * 16;

    // prefetch base: warp's 16-row block start, next chunk. Lane l covers line
    // (row = l>>1, half = l&1): 16 rows x 2 x 128B = this warp's entire A slice.
    const char* pfb = (const char*)(hgp - tau - (size_t)g * 16) + (size_t)(lane >> 1) * 256
                      + (size_t)(lane & 1) * 128;

    for (int ch = cA; ch < cB; ch++) {
        const bool fullc = (ch < nfull);
        const bool vg = fullc || (rg < n);
        const bool v8 = fullc || (rg + 8 < n);
        const float4 z4 = make_float4(0.f, 0.f, 0.f, 0.f);

        // ---- A loads: 8x LDG.128 streaming, front-batched (rows rg, rg+8) ----
        float4 aL[4], aH[4];
        if (fullc) {
            #pragma unroll
            for (int S = 0; S < 4; S++) aL[S] = __ldcs(hgp + 4 * S);
            #pragma unroll
            for (int S = 0; S < 4; S++) aH[S] = __ldcs(hgp + 128 + 4 * S);
        } else {
            #pragma unroll
            for (int S = 0; S < 4; S++) aL[S] = vg ? __ldcs(hgp + 4 * S) : z4;
            #pragma unroll
            for (int S = 0; S < 4; S++) aH[S] = v8 ? __ldcs(hgp + 128 + 4 * S) : z4;
        }

        // ---- prefetch NEXT chunk into L2 (no regs, no scoreboard) ----
        if (ch + 1 < nfull) {
            prefetch_l2(pfb + 32768);                 // 128 rows * 256 B ahead
            if (lane == 0) prefetch_l2((const char*)(gp + 128));
            if (lane == 1) prefetch_l2((const char*)(pp + 128));
        }

        float d2a = 0.f, d2b = 0.f;
        if (vg) {
            float2 gg = __ldcs(gp), qq = __ldcs(pp);
            float dx = gg.x - qq.x, dy = gg.y - qq.y;
            d2a = sqrtf(dx * dx + dy * dy);
        }
        if (v8) {
            float2 gg = __ldcs(gp + 8), qq = __ldcs(pp + 8);
            float dx = gg.x - qq.x, dy = gg.y - qq.y;
            d2b = sqrtf(dx * dx + dy * dy);
        }

        // ---- convert A to fp16 fragments ----
        uint32_t a0[4], a1[4], a2[4], a3[4];
        #pragma unroll
        for (int S = 0; S < 4; S++) {
            a0[S] = pack_h2(aL[S].x, aL[S].y);
            a2[S] = pack_h2(aL[S].z, aL[S].w);
            a1[S] = pack_h2(aH[S].x, aH[S].y);
            a3[S] = pack_h2(aH[S].z, aH[S].w);
        }

        // ---- 32 MMAs: 4 S x 8 n-tiles, all operands in registers ----
        float acc[8][4] = {{0,0,0,0},{0,0,0,0},{0,0,0,0},{0,0,0,0},
                           {0,0,0,0},{0,0,0,0},{0,0,0,0},{0,0,0,0}};
        #pragma unroll
        for (int S = 0; S < 4; S++) {
            #pragma unroll
            for (int nt = 0; nt < 8; nt++)
                mma_f16(acc[nt], a0[S], a1[S], a2[S], a3[S], bf[nt][S].x, bf[nt][S].y);
        }

        // ---- epilogue: four streaming STG.128 per row ----
        #pragma unroll
        for (int sgg = 0; sgg < 4; sgg++) {
            const int f4i = sgg * 4 + tau;
            float4 cc = sC4[f4i];
            float4 uu = sU4[f4i];
            if (vg) {
                float4 o;
                o.x = sigmoid_fast(fmaf(d2a, uu.x, acc[2*sgg][0]   + cc.x));
                o.y = sigmoid_fast(fmaf(d2a, uu.y, acc[2*sgg][1]   + cc.y));
                o.z = sigmoid_fast(fmaf(d2a, uu.z, acc[2*sgg+1][0] + cc.z));
                o.w = sigmoid_fast(fmaf(d2a, uu.w, acc[2*sgg+1][1] + cc.w));
                __stcs(op + f4i, o);
            }
            if (v8) {
                float4 o;
                o.x = sigmoid_fast(fmaf(d2b, uu.x, acc[2*sgg][2]   + cc.x));
                o.y = sigmoid_fast(fmaf(d2b, uu.y, acc[2*sgg][3]   + cc.y));
                o.z = sigmoid_fast(fmaf(d2b, uu.z, acc[2*sgg+1][2] + cc.z));
                o.w = sigmoid_fast(fmaf(d2b, uu.w, acc[2*sgg+1][3] + cc.w));
                __stcs(op + 128 + f4i, o);
            }
        }

        rg  += 128;
        hgp += 2048;    // 128 rows * 16 float4
        pfb += 32768;
        gp  += 128;
        pp  += 128;
        op  += 2048;
    }

    // ---- row-idx pass-through fixup (owning CTA only, after its stores) ----
    {
        const int cidx = idx >> 7;                  // chunk containing row idx
        if (cidx >= cA && cidx < cB) {              // CTA-uniform condition
            __syncthreads();                        // order vs this CTA's stores
            if (t < 16)
                out4[(size_t)idx * 16 + t] = h4[(size_t)idx * 16 + t];
        }
    }
}

// ---------------- launch ----------------

extern "C" void kernel_launch(void* const* d_in, const int* in_sizes, int n_in,
                              void* d_out, int out_size)
{
    const float* h    = (const float*)d_in[0];  // (N, 64)
    const float* ghs  = (const float*)d_in[1];  // (64,)
    const float* goal = (const float*)d_in[2];  // (N, 2)
    const float* pos  = (const float*)d_in[3];  // (N, 2)
    const float* Wemb = (const float*)d_in[4];  // (32, 2)
    const float* bemb = (const float*)d_in[5];  // (32,)
    const float* Wfc  = (const float*)d_in[6];  // (64, 192)
    const float* bfc  = (const float*)d_in[7];  // (64,)
    const int*   idx  = (const int*)d_in[8];    // scalar
    float* out = (float*)d_out;                 // N*64 h_out then 64 goal_out

    int n = in_sizes[0] / HDIM;
    int nch = (n + 127) / 128;
    int grid = 296;                              // 148 SMs x 2 CTAs (persistent)
    if (grid > nch) grid = nch;

    gate_kernel<<<grid, 256>>>(h, ghs, goal, pos, Wemb, bemb, Wfc, bfc, idx, out, n);
}